// round 3
// baseline (speedup 1.0000x reference)
#include <cuda_runtime.h>
#include <math.h>
#include <stdint.h>

#define NB   12000
#define Dd   64
#define Bb   1024
#define Ll   20
#define BKk  10
#define NOLDn 20

// ---------------- scratch (device globals; no allocation allowed) ----------
__device__ float g_baskets[4 * Bb * Ll * Dd];   // 20 MB
__device__ float g_s1[4 * Bb * Dd];
__device__ float g_s2[4 * Bb * Dd];
__device__ float g_s3[4 * Bb * Dd];
__device__ float g_lvec[4 * Bb * Dd];
__device__ float g_feach[4 * Bb * Dd];
__device__ float g_Afin[Bb * 128];              // [final | e_user]
__device__ float g_Bmat[128 * NB];              // [e_all^T ; u_w]

__device__ __forceinline__ float sigmoidf(float x) { return 1.f / (1.f + expf(-x)); }

// packed f32x2 FMA: acc = a * b + acc (elementwise on {lo,hi})
__device__ __forceinline__ void fma2(unsigned long long& acc,
                                     unsigned long long a, unsigned long long b) {
    asm("fma.rn.f32x2 %0, %1, %2, %0;" : "+l"(acc) : "l"(a), "l"(b));
}
__device__ __forceinline__ unsigned long long dup2(float x) {
    unsigned long long r;
    asm("mov.b64 %0, {%1, %1};" : "=l"(r) : "f"(x));
    return r;
}
__device__ __forceinline__ void unpack2(unsigned long long v, float& lo, float& hi) {
    asm("mov.b64 {%0, %1}, %2;" : "=f"(lo), "=f"(hi) : "l"(v));
}

// 64-thread block reduction (broadcast result to all threads)
__device__ __forceinline__ float block64_reduce(float v, float* sbuf, int d) {
    sbuf[d] = v;
    __syncthreads();
    if (d < 32) {
        float r = sbuf[d] + sbuf[d + 32];
#pragma unroll
        for (int o = 16; o > 0; o >>= 1) r += __shfl_down_sync(0xffffffffu, r, o);
        if (d == 0) sbuf[0] = r;
    }
    __syncthreads();
    float r = sbuf[0];
    __syncthreads();
    return r;
}

// ---------------- kernel A: baskets gather-sum ------------------------------
__global__ void k_baskets(const int* __restrict__ click, const int* __restrict__ favor,
                          const int* __restrict__ cart, const int* __restrict__ buy,
                          const float* __restrict__ item_emb) {
    int t = threadIdx.x;
    int d = t & 63;
    int row = blockIdx.x * 4 + (t >> 6);     // row in [0, 4*B*L)
    int n = row / (Bb * Ll);
    int rem = row - n * (Bb * Ll);           // b*L + l
    const int* idx;
    if (n == 0) idx = click; else if (n == 1) idx = favor;
    else if (n == 2) idx = cart; else idx = buy;
    idx += rem * BKk;
    float s = 0.f;
#pragma unroll
    for (int k = 0; k < BKk; k++) s += item_emb[idx[k] * Dd + d];
    g_baskets[row * Dd + d] = s;
}

// ---------------- kernel B: per-(n,b) attention + EMA + gate ----------------
__global__ void __launch_bounds__(64)
k_seq(const int* __restrict__ userData, const float* __restrict__ user_emb,
      const float* __restrict__ user_wd, const float* __restrict__ Wk,
      const float* __restrict__ bk, const float* __restrict__ gate_w,
      const float* __restrict__ gate_b, const float* __restrict__ alpha) {
    int nb = blockIdx.x;                 // n*B + b
    int n = nb / Bb, b = nb - n * Bb;
    int d = threadIdx.x;                 // 0..63

    __shared__ float sb[Ll][Dd];
    __shared__ float sred[Dd];
    __shared__ float s_attn[Ll];

    const float* bas = g_baskets + (size_t)nb * Ll * Dd;
#pragma unroll
    for (int l = 0; l < Ll; l++) sb[l][d] = bas[l * Dd + d];

    float wkreg[Dd];
#pragma unroll
    for (int e = 0; e < Dd; e++) wkreg[e] = Wk[n * Dd * Dd + e * Dd + d];

    int u = userData[b];
    float eu = user_emb[u * Dd + d];
    float bkd = bk[n * Dd + d];
    __syncthreads();

    for (int l = 0; l < Ll; l++) {
        float kd = bkd;
#pragma unroll
        for (int e = 0; e < Dd; e++) kd += sb[l][e] * wkreg[e];
        kd = fmaxf(kd, 0.f);
        float sc = block64_reduce(eu * kd, sred, d);
        float rs = block64_reduce(sb[l][d], sred, d);
        if (d == 0) s_attn[l] = (rs != 0.f) ? sc * 0.125f : -1000000000.0f;
        __syncthreads();
    }

    // softmax over 20 (redundant per thread)
    float m = -3.4e38f;
#pragma unroll
    for (int l = 0; l < Ll; l++) m = fmaxf(m, s_attn[l]);
    float ex[Ll];
    float Z = 0.f;
#pragma unroll
    for (int l = 0; l < Ll; l++) { ex[l] = expf(s_attn[l] - m); Z += ex[l]; }
    float invZ = 1.f / Z;
    float lv = 0.f;
#pragma unroll
    for (int l = 0; l < Ll; l++) lv += ex[l] * invZ * sb[l][d];

    // EMA chains
    float w1 = sigmoidf(user_wd[u * 8 + 2 * n]);
    float w2 = sigmoidf(user_wd[u * 8 + 2 * n + 1]);
    float coef = 1.f - w2 * w1;
    float h1 = sb[0][d];
#pragma unroll
    for (int l = 1; l < Ll; l++) h1 = w1 * h1 + coef * sb[l][d];
    float h2 = sb[Ll / 2][d];
#pragma unroll
    for (int l = Ll / 2 + 1; l < Ll; l++) h2 = w1 * h2 + coef * sb[l][d];
    float h3 = w1 * sb[Ll - 2][d] + coef * sb[Ll - 1][d];

    float a0 = alpha[0], a1 = alpha[1];
    float fn = h1 + a0 * (h1 - h2) + a1 * (h1 - h3);

    float gsum = block64_reduce(fn * gate_w[d] + lv * gate_w[Dd + d], sred, d);
    float g = sigmoidf(gsum + gate_b[0]);
    float fe = g * fn + (1.f - g) * lv;

    int off = nb * Dd + d;
    g_s1[off] = h1; g_s2[off] = h2; g_s3[off] = h3;
    g_lvec[off] = lv; g_feach[off] = fe;
}

// ---------------- kernel C: mixture over behaviors --------------------------
__global__ void __launch_bounds__(64)
k_mix(const int* __restrict__ userData, const float* __restrict__ user_emb,
      const float* __restrict__ w_mix, const float* __restrict__ alpha,
      const float* __restrict__ gate_w, const float* __restrict__ gate_b) {
    int b = blockIdx.x;
    int d = threadIdx.x;
    __shared__ float sred[Dd];

    float w[4][4];
#pragma unroll
    for (int i = 0; i < 4; i++) {
        float mx = -3.4e38f;
#pragma unroll
        for (int j = 0; j < 4; j++) mx = fmaxf(mx, w_mix[i * 4 + j]);
        float Z = 0.f;
#pragma unroll
        for (int j = 0; j < 4; j++) { w[i][j] = expf(w_mix[i * 4 + j] - mx); Z += w[i][j]; }
        float inv = 1.f / Z;
#pragma unroll
        for (int j = 0; j < 4; j++) w[i][j] *= inv;
    }

    float s1m = 0.f, s2m = 0.f, s3m = 0.f, lm = 0.f;
#pragma unroll
    for (int n = 0; n < 4; n++) {
        int off = (n * Bb + b) * Dd + d;
        s1m += w[0][n] * g_s1[off];
        s2m += w[1][n] * g_s2[off];
        s3m += w[2][n] * g_s3[off];
        lm  += w[3][n] * g_lvec[off];
    }
    float a0 = alpha[0], a1 = alpha[1];
    float fin_ = s1m + a0 * (s1m - s2m) + a1 * (s1m - s3m);

    float gsum = block64_reduce(fin_ * gate_w[d] + lm * gate_w[Dd + d], sred, d);
    float gm = sigmoidf(gsum + gate_b[0]);
    float fin = gm * fin_ + (1.f - gm) * lm;

    g_Afin[b * 128 + d] = fin;
    g_Afin[b * 128 + Dd + d] = user_emb[userData[b] * Dd + d];
}

// ---------------- kernel: build fused B matrix [e_all^T ; u_w] --------------
__global__ void k_bmat(const float* __restrict__ item_emb, const float* __restrict__ u_w) {
    int i = blockIdx.x * blockDim.x + threadIdx.x;
    if (i >= 128 * NB) return;
    int k = i / NB, e = i - k * NB;
    g_Bmat[i] = (k < Dd) ? item_emb[(e + 1) * Dd + k] : u_w[(k - Dd) * NB + e];
}

// ---------------- kernel D: score GEMM (M=1024, N=12000, K=128) -------------
__global__ void __launch_bounds__(256)
k_score(const float* __restrict__ u_b, float* __restrict__ out) {
    __shared__ float As[32][132];   // As[k][row]
    __shared__ float Bs[32][132];   // Bs[k][col]
    int t = threadIdx.x;
    int i0 = blockIdx.y * 128, j0 = blockIdx.x * 128;
    int tx = t & 15, ty = t >> 4;
    unsigned long long acc2[4][8];  // pairs along M: m = ty*8 + 2*mp + {lo,hi}
#pragma unroll
    for (int mp = 0; mp < 4; mp++)
#pragma unroll
        for (int nn = 0; nn < 8; nn++) acc2[mp][nn] = 0ull;

    for (int kc = 0; kc < 128; kc += 32) {
#pragma unroll
        for (int it = 0; it < 16; it++) {
            int idx = it * 256 + t;
            int r = idx >> 5, kk = idx & 31;
            As[kk][r] = g_Afin[(i0 + r) * 128 + kc + kk];
        }
#pragma unroll
        for (int it = 0; it < 16; it++) {
            int idx = it * 256 + t;
            int kk = idx >> 7, e = idx & 127;
            int j = j0 + e;
            Bs[kk][e] = (j < NB) ? g_Bmat[(kc + kk) * NB + j] : 0.f;
        }
        __syncthreads();
#pragma unroll
        for (int kk = 0; kk < 32; kk++) {
            float bbv[8];
            *(float4*)&bbv[0] = *(const float4*)&Bs[kk][tx * 8];
            *(float4*)&bbv[4] = *(const float4*)&Bs[kk][tx * 8 + 4];
            unsigned long long ap[4];
#pragma unroll
            for (int mp = 0; mp < 4; mp++)
                ap[mp] = *(const unsigned long long*)&As[kk][ty * 8 + 2 * mp];
            unsigned long long bd[8];
#pragma unroll
            for (int nn = 0; nn < 8; nn++) bd[nn] = dup2(bbv[nn]);
#pragma unroll
            for (int mp = 0; mp < 4; mp++)
#pragma unroll
                for (int nn = 0; nn < 8; nn++) fma2(acc2[mp][nn], ap[mp], bd[nn]);
        }
        __syncthreads();
    }
#pragma unroll
    for (int mp = 0; mp < 4; mp++) {
        float r0[8], r1[8];
#pragma unroll
        for (int nn = 0; nn < 8; nn++) unpack2(acc2[mp][nn], r0[nn], r1[nn]);
        int i = i0 + ty * 8 + 2 * mp;
#pragma unroll
        for (int n4 = 0; n4 < 8; n4 += 4) {
            int j = j0 + tx * 8 + n4;
            if (j < NB) {
                float b0 = u_b[j], b1 = u_b[j + 1], b2 = u_b[j + 2], b3 = u_b[j + 3];
                float4 v0 = make_float4(r0[n4] + b0, r0[n4 + 1] + b1, r0[n4 + 2] + b2, r0[n4 + 3] + b3);
                float4 v1 = make_float4(r1[n4] + b0, r1[n4 + 1] + b1, r1[n4 + 2] + b2, r1[n4 + 3] + b3);
                *(float4*)&out[(size_t)i * NB + j] = v0;
                *(float4*)&out[(size_t)(i + 1) * NB + j] = v1;
            }
        }
    }
}

// ---------------- kernel E: sim = e_all @ e_all^T (triangular grid) ---------
__global__ void __launch_bounds__(256)
k_sim(const float* __restrict__ item_emb, float* __restrict__ out) {
    __shared__ float As[32][132];
    __shared__ float Bs[32][132];
    int lid = blockIdx.x;
    // decode linear id -> (bi <= bj) upper-triangle tile pair
    int r = (int)((sqrtf(8.f * (float)lid + 1.f) - 1.f) * 0.5f);
    while ((r + 1) * (r + 2) / 2 <= lid) r++;
    while (r * (r + 1) / 2 > lid) r--;
    int bi = lid - r * (r + 1) / 2;   // <= r
    int bj = r;
    int i0 = bi * 128, j0 = bj * 128;

    const float* eall = item_emb + Dd;   // row e -> item_emb[(e+1)*64]
    int t = threadIdx.x;
    int tx = t & 15, ty = t >> 4;
    unsigned long long acc2[4][8];
#pragma unroll
    for (int mp = 0; mp < 4; mp++)
#pragma unroll
        for (int nn = 0; nn < 8; nn++) acc2[mp][nn] = 0ull;

    for (int kc = 0; kc < 64; kc += 32) {
#pragma unroll
        for (int it = 0; it < 16; it++) {
            int idx = it * 256 + t;
            int rr = idx >> 5, kk = idx & 31;
            int gi = i0 + rr; if (gi > NB - 1) gi = NB - 1;
            As[kk][rr] = eall[gi * Dd + kc + kk];
        }
#pragma unroll
        for (int it = 0; it < 16; it++) {
            int idx = it * 256 + t;
            int rr = idx >> 5, kk = idx & 31;
            int gj = j0 + rr; if (gj > NB - 1) gj = NB - 1;
            Bs[kk][rr] = eall[gj * Dd + kc + kk];
        }
        __syncthreads();
#pragma unroll
        for (int kk = 0; kk < 32; kk++) {
            float bbv[8];
            *(float4*)&bbv[0] = *(const float4*)&Bs[kk][tx * 8];
            *(float4*)&bbv[4] = *(const float4*)&Bs[kk][tx * 8 + 4];
            unsigned long long ap[4];
#pragma unroll
            for (int mp = 0; mp < 4; mp++)
                ap[mp] = *(const unsigned long long*)&As[kk][ty * 8 + 2 * mp];
            unsigned long long bd[8];
#pragma unroll
            for (int nn = 0; nn < 8; nn++) bd[nn] = dup2(bbv[nn]);
#pragma unroll
            for (int mp = 0; mp < 4; mp++)
#pragma unroll
                for (int nn = 0; nn < 8; nn++) fma2(acc2[mp][nn], ap[mp], bd[nn]);
        }
        __syncthreads();
    }

    // unpack to accf for stores
    float accf[8][8];
#pragma unroll
    for (int mp = 0; mp < 4; mp++)
#pragma unroll
        for (int nn = 0; nn < 8; nn++)
            unpack2(acc2[mp][nn], accf[2 * mp][nn], accf[2 * mp + 1][nn]);

    // direct store (bi,bj)
#pragma unroll
    for (int m = 0; m < 8; m++) {
        int i = i0 + ty * 8 + m;
        if (i < NB) {
#pragma unroll
            for (int n4 = 0; n4 < 8; n4 += 4) {
                int j = j0 + tx * 8 + n4;
                if (j < NB) {
                    float4 v = make_float4(accf[m][n4], accf[m][n4 + 1], accf[m][n4 + 2], accf[m][n4 + 3]);
                    *(float4*)&out[(size_t)i * NB + j] = v;
                }
            }
        }
    }
    // mirrored store (bj,bi) for off-diagonal tiles
    if (bi != bj) {
#pragma unroll
        for (int nn = 0; nn < 8; nn++) {
            int j = j0 + tx * 8 + nn;
            if (j < NB) {
                float4 v0 = make_float4(accf[0][nn], accf[1][nn], accf[2][nn], accf[3][nn]);
                float4 v1 = make_float4(accf[4][nn], accf[5][nn], accf[6][nn], accf[7][nn]);
                *(float4*)&out[(size_t)j * NB + i0 + ty * 8] = v0;
                *(float4*)&out[(size_t)j * NB + i0 + ty * 8 + 4] = v1;
            }
        }
    }
}

// ---------------- kernel G: sparse old-items corrections --------------------
__global__ void __launch_bounds__(128)
k_sparse(const int* __restrict__ oldItems, const float* __restrict__ item_emb,
         float* __restrict__ out) {
    int b = blockIdx.x;
    int t = threadIdx.x;
    int n = t >> 5, lane = t & 31;
    __shared__ int sh_old[4][NOLDn];
    __shared__ float sh_fin[Dd];
    if (t < Dd) sh_fin[t] = g_Afin[b * 128 + t];
    if (t < 4 * NOLDn) {
        int n2 = t / NOLDn, j = t - n2 * NOLDn;
        sh_old[n2][j] = oldItems[(n2 * Bb + b) * NOLDn + j];
    }
    __syncthreads();

    int d0 = lane, d1 = lane + 32;
    float diff0 = g_feach[(n * Bb + b) * Dd + d0] - sh_fin[d0];
    float diff1 = g_feach[(n * Bb + b) * Dd + d1] - sh_fin[d1];
    const float* eall = item_emb + Dd;

    for (int j = 0; j < NOLDn; j++) {
        int e = sh_old[n][j];
        bool dup = false;
        for (int j2 = 0; j2 < j; j2++) if (sh_old[n][j2] == e) dup = true;
        if (dup) continue;
        float v = diff0 * eall[e * Dd + d0] + diff1 * eall[e * Dd + d1];
#pragma unroll
        for (int o = 16; o > 0; o >>= 1) v += __shfl_down_sync(0xffffffffu, v, o);
        if (lane == 0) atomicAdd(&out[(size_t)b * NB + e], v);
    }
}

// ---------------- kernel F: omiga copy ---------------------------------------
__global__ void k_omiga(const float* __restrict__ omiga, float* __restrict__ out) {
    int i = blockIdx.x * blockDim.x + threadIdx.x;
    if (i < NB) out[i] = omiga[i + 1];
}

// ---------------- launch ------------------------------------------------------
extern "C" void kernel_launch(void* const* d_in, const int* in_sizes, int n_in,
                              void* d_out, int out_size) {
    const int* click = (const int*)d_in[0];
    const int* favor = (const int*)d_in[1];
    const int* cart  = (const int*)d_in[2];
    const int* buy   = (const int*)d_in[3];
    const int* user  = (const int*)d_in[4];
    const int* olds  = (const int*)d_in[5];
    const float* item_emb = (const float*)d_in[6];
    const float* user_emb = (const float*)d_in[7];
    const float* user_wd  = (const float*)d_in[8];
    const float* omiga    = (const float*)d_in[9];
    const float* w_mix    = (const float*)d_in[10];
    const float* alpha    = (const float*)d_in[11];
    const float* gate_w   = (const float*)d_in[12];
    const float* gate_b   = (const float*)d_in[13];
    const float* Wk       = (const float*)d_in[14];
    const float* bk       = (const float*)d_in[15];
    const float* u_w      = (const float*)d_in[16];
    const float* u_b      = (const float*)d_in[17];
    float* out = (float*)d_out;

    k_baskets<<<4 * Bb * Ll / 4, 256>>>(click, favor, cart, buy, item_emb);
    k_seq<<<4 * Bb, 64>>>(user, user_emb, user_wd, Wk, bk, gate_w, gate_b, alpha);
    k_mix<<<Bb, 64>>>(user, user_emb, w_mix, alpha, gate_w, gate_b);
    k_bmat<<<(128 * NB + 255) / 256, 256>>>(item_emb, u_w);

    dim3 gs((NB + 127) / 128, Bb / 128);
    k_score<<<gs, 256>>>(u_b, out);
    k_sparse<<<Bb, 128>>>(olds, item_emb, out);

    int nbT = (NB + 127) / 128;               // 94
    k_sim<<<nbT * (nbT + 1) / 2, 256>>>(item_emb, out + (size_t)Bb * NB);
    k_omiga<<<(NB + 255) / 256, 256>>>(omiga, out + (size_t)Bb * NB + (size_t)NB * NB);
}

// round 4
// speedup vs baseline: 1.7324x; 1.7324x over previous
#include <cuda_runtime.h>
#include <math.h>
#include <stdint.h>

#define NB   12000
#define Dd   64
#define Bb   1024
#define Ll   20
#define BKk  10
#define NOLDn 20

// ---------------- scratch (device globals; no allocation allowed) ----------
__device__ float g_baskets[4 * Bb * Ll * Dd];   // 20 MB
__device__ float g_s1[4 * Bb * Dd];
__device__ float g_s2[4 * Bb * Dd];
__device__ float g_s3[4 * Bb * Dd];
__device__ float g_lvec[4 * Bb * Dd];
__device__ float g_feach[4 * Bb * Dd];
__device__ float g_Afin[Bb * 128];              // [final | e_user]
__device__ float g_uwT[NB * 64];                // u_w transposed: [e][k]

__device__ __forceinline__ float sigmoidf(float x) { return 1.f / (1.f + expf(-x)); }

// ===================== 3xTF32 mma.sync GEMM =================================
// tf32 truncation (round-toward-zero on mantissa bits below 2^-13)
__device__ __forceinline__ float tf32_trunc(float a) {
    return __uint_as_float(__float_as_uint(a) & 0xFFFFE000u);
}

__device__ __forceinline__ void mma8(float* d, const uint32_t* a, const uint32_t* b) {
    asm volatile(
        "mma.sync.aligned.m16n8k8.row.col.f32.tf32.tf32.f32 "
        "{%0,%1,%2,%3}, {%4,%5,%6,%7}, {%8,%9}, {%0,%1,%2,%3};"
        : "+f"(d[0]), "+f"(d[1]), "+f"(d[2]), "+f"(d[3])
        : "r"(a[0]), "r"(a[1]), "r"(a[2]), "r"(a[3]), "r"(b[0]), "r"(b[1]));
}

// Load a 128x64 fp32 tile (rows clamped), split into tf32 hi/lo, store
// interleaved into smem: S[row*136 + 2k + {0=hi,1=lo}]. Conflict-free STS.128.
__device__ __forceinline__ void load_split(float* __restrict__ S,
                                           const float* __restrict__ src,
                                           long row0, long rows, int stride, int tid) {
    int lane = tid & 31, w = tid >> 5;
    int rr = lane >> 3;            // 0..3
    int kk = (lane & 7) * 2;       // 0,2,..,14
#pragma unroll
    for (int grp = 0; grp < 4; grp++) {
        int row = (w + grp * 8) * 4 + rr;
        long gr = row0 + row; if (gr >= rows) gr = rows - 1;
        const float* base = src + gr * (long)stride;
#pragma unroll
        for (int kc = 0; kc < 4; kc++) {
            int k = kc * 16 + kk;
            float2 a = *(const float2*)&base[k];
            float hx = tf32_trunc(a.x);
            float lx = tf32_trunc(a.x - hx);
            float hy = tf32_trunc(a.y);
            float ly = tf32_trunc(a.y - hy);
            *(float4*)&S[row * 136 + 2 * k] = make_float4(hx, lx, hy, ly);
        }
    }
}

// Generic tile GEMM: C[i][j] = sum_h sum_k A_h[i][k] * B_h[j][k] (+ bias[j]).
// Tiles 128x128, K=64 per half (1 or 2 halves). triangular=1: blockIdx.x is a
// linear upper-triangle tile id; result mirrored to (j,i) for off-diagonal.
__global__ void __launch_bounds__(256)
k_mma(const float* __restrict__ A1, const float* __restrict__ A2, int a_stride, long a_rows,
      const float* __restrict__ B1, const float* __restrict__ B2, long b_rows,
      float* __restrict__ C, const float* __restrict__ bias, int triangular)
{
    extern __shared__ float smf[];
    float* As = smf;               // 17408 floats
    float* Bs = smf + 17408;

    int tid = threadIdx.x;
    int bi, bj;
    if (triangular) {
        int lid = blockIdx.x;
        int r = (int)((sqrtf(8.f * (float)lid + 1.f) - 1.f) * 0.5f);
        while ((r + 1) * (r + 2) / 2 <= lid) r++;
        while (r * (r + 1) / 2 > lid) r--;
        bi = lid - r * (r + 1) / 2;
        bj = r;
    } else {
        bi = blockIdx.y; bj = blockIdx.x;
    }
    long i0 = (long)bi * 128, j0 = (long)bj * 128;

    int lane = tid & 31, wid = tid >> 5;
    int g = lane >> 2, tig = lane & 3;
    int wm = wid & 3, wn = wid >> 2;   // 4 x 2 warp grid -> 32x64 per warp

    float acc[2][8][4];
#pragma unroll
    for (int mt = 0; mt < 2; mt++)
#pragma unroll
        for (int nt = 0; nt < 8; nt++)
#pragma unroll
            for (int q = 0; q < 4; q++) acc[mt][nt][q] = 0.f;

    int halves = (A2 != nullptr) ? 2 : 1;
    for (int h = 0; h < halves; h++) {
        if (h) __syncthreads();
        load_split(As, h ? A2 : A1, i0, a_rows, a_stride, tid);
        load_split(Bs, h ? B2 : B1, j0, b_rows, 64, tid);
        __syncthreads();

#pragma unroll
        for (int k0 = 0; k0 < 64; k0 += 8) {
            uint32_t ah[2][4], al[2][4];
#pragma unroll
            for (int mt = 0; mt < 2; mt++) {
                const float* rp0 = As + (wm * 32 + mt * 16 + g) * 136 + 2 * (k0 + tig);
                const float* rp1 = rp0 + 8 * 136;
                float2 v0 = *(const float2*)rp0;
                float2 v1 = *(const float2*)rp1;
                float2 v2 = *(const float2*)(rp0 + 8);
                float2 v3 = *(const float2*)(rp1 + 8);
                ah[mt][0] = __float_as_uint(v0.x); al[mt][0] = __float_as_uint(v0.y);
                ah[mt][1] = __float_as_uint(v1.x); al[mt][1] = __float_as_uint(v1.y);
                ah[mt][2] = __float_as_uint(v2.x); al[mt][2] = __float_as_uint(v2.y);
                ah[mt][3] = __float_as_uint(v3.x); al[mt][3] = __float_as_uint(v3.y);
            }
            uint32_t bh[8][2], bl[8][2];
#pragma unroll
            for (int nt = 0; nt < 8; nt++) {
                const float* cp = Bs + (wn * 64 + nt * 8 + g) * 136 + 2 * (k0 + tig);
                float2 u0 = *(const float2*)cp;
                float2 u1 = *(const float2*)(cp + 8);
                bh[nt][0] = __float_as_uint(u0.x); bl[nt][0] = __float_as_uint(u0.y);
                bh[nt][1] = __float_as_uint(u1.x); bl[nt][1] = __float_as_uint(u1.y);
            }
#pragma unroll
            for (int mt = 0; mt < 2; mt++)
#pragma unroll
                for (int nt = 0; nt < 8; nt++) {
                    mma8(acc[mt][nt], ah[mt], bh[nt]);
                    mma8(acc[mt][nt], ah[mt], bl[nt]);
                    mma8(acc[mt][nt], al[mt], bh[nt]);
                }
        }
    }

    // ---------------- epilogue: smem-staged coalesced stores ----------------
    float* st = As;   // reuse (128*133 = 17024 <= 17408)
    __syncthreads();
#pragma unroll
    for (int mt = 0; mt < 2; mt++)
#pragma unroll
        for (int nt = 0; nt < 8; nt++) {
            int R  = wm * 32 + mt * 16 + g;
            int Cc = wn * 64 + nt * 8 + 2 * tig;
            st[R * 133 + Cc]           = acc[mt][nt][0];
            st[R * 133 + Cc + 1]       = acc[mt][nt][1];
            st[(R + 8) * 133 + Cc]     = acc[mt][nt][2];
            st[(R + 8) * 133 + Cc + 1] = acc[mt][nt][3];
        }
    __syncthreads();

    {
        int cc = tid & 127, rb = tid >> 7;
        long gj = j0 + cc;
        float bv = 0.f;
        if (bias && gj < b_rows) bv = bias[gj];
#pragma unroll 8
        for (int q = 0; q < 64; q++) {
            int r = rb + 2 * q;
            long gi = i0 + r;
            if (gi < a_rows && gj < b_rows)
                C[gi * (long)NB + gj] = st[r * 133 + cc] + bv;
        }
    }

    if (triangular && bi != bj) {
        __syncthreads();
#pragma unroll
        for (int mt = 0; mt < 2; mt++)
#pragma unroll
            for (int nt = 0; nt < 8; nt++) {
                int R  = wm * 32 + mt * 16 + g;
                int Cc = wn * 64 + nt * 8 + 2 * tig;
                st[Cc * 133 + R]           = acc[mt][nt][0];
                st[(Cc + 1) * 133 + R]     = acc[mt][nt][1];
                st[Cc * 133 + R + 8]       = acc[mt][nt][2];
                st[(Cc + 1) * 133 + R + 8] = acc[mt][nt][3];
            }
        __syncthreads();
        int ii = tid & 127, jb = tid >> 7;
        long gi = i0 + ii;
#pragma unroll 8
        for (int q = 0; q < 64; q++) {
            int jj = jb + 2 * q;
            long gj = j0 + jj;
            if (gi < a_rows && gj < b_rows)
                C[gj * (long)NB + gi] = st[jj * 133 + ii];
        }
    }
}

// ---------------- u_w transpose: g_uwT[e][k] = u_w[k][e] --------------------
__global__ void __launch_bounds__(1024)
k_uwT(const float* __restrict__ u_w) {
    __shared__ float t[32][33];
    int e0 = blockIdx.x * 32, k0 = blockIdx.y * 32;
    int tx = threadIdx.x & 31, ty = threadIdx.x >> 5;
    t[ty][tx] = u_w[(long)(k0 + ty) * NB + e0 + tx];
    __syncthreads();
    g_uwT[(long)(e0 + ty) * 64 + k0 + tx] = t[tx][ty];
}

// 64-thread block reduction (broadcast result to all threads)
__device__ __forceinline__ float block64_reduce(float v, float* sbuf, int d) {
    sbuf[d] = v;
    __syncthreads();
    if (d < 32) {
        float r = sbuf[d] + sbuf[d + 32];
#pragma unroll
        for (int o = 16; o > 0; o >>= 1) r += __shfl_down_sync(0xffffffffu, r, o);
        if (d == 0) sbuf[0] = r;
    }
    __syncthreads();
    float r = sbuf[0];
    __syncthreads();
    return r;
}

// ---------------- kernel A: baskets gather-sum ------------------------------
__global__ void k_baskets(const int* __restrict__ click, const int* __restrict__ favor,
                          const int* __restrict__ cart, const int* __restrict__ buy,
                          const float* __restrict__ item_emb) {
    int t = threadIdx.x;
    int d = t & 63;
    int row = blockIdx.x * 4 + (t >> 6);
    int n = row / (Bb * Ll);
    int rem = row - n * (Bb * Ll);
    const int* idx;
    if (n == 0) idx = click; else if (n == 1) idx = favor;
    else if (n == 2) idx = cart; else idx = buy;
    idx += rem * BKk;
    float s = 0.f;
#pragma unroll
    for (int k = 0; k < BKk; k++) s += item_emb[idx[k] * Dd + d];
    g_baskets[row * Dd + d] = s;
}

// ---------------- kernel B: per-(n,b) attention + EMA + gate ----------------
__global__ void __launch_bounds__(64)
k_seq(const int* __restrict__ userData, const float* __restrict__ user_emb,
      const float* __restrict__ user_wd, const float* __restrict__ Wk,
      const float* __restrict__ bk, const float* __restrict__ gate_w,
      const float* __restrict__ gate_b, const float* __restrict__ alpha) {
    int nb = blockIdx.x;
    int n = nb / Bb, b = nb - n * Bb;
    int d = threadIdx.x;

    __shared__ float sb[Ll][Dd];
    __shared__ float sred[Dd];
    __shared__ float s_attn[Ll];

    const float* bas = g_baskets + (size_t)nb * Ll * Dd;
#pragma unroll
    for (int l = 0; l < Ll; l++) sb[l][d] = bas[l * Dd + d];

    float wkreg[Dd];
#pragma unroll
    for (int e = 0; e < Dd; e++) wkreg[e] = Wk[n * Dd * Dd + e * Dd + d];

    int u = userData[b];
    float eu = user_emb[u * Dd + d];
    float bkd = bk[n * Dd + d];
    __syncthreads();

    for (int l = 0; l < Ll; l++) {
        float kd = bkd;
#pragma unroll
        for (int e = 0; e < Dd; e++) kd += sb[l][e] * wkreg[e];
        kd = fmaxf(kd, 0.f);
        float sc = block64_reduce(eu * kd, sred, d);
        float rs = block64_reduce(sb[l][d], sred, d);
        if (d == 0) s_attn[l] = (rs != 0.f) ? sc * 0.125f : -1000000000.0f;
        __syncthreads();
    }

    float m = -3.4e38f;
#pragma unroll
    for (int l = 0; l < Ll; l++) m = fmaxf(m, s_attn[l]);
    float ex[Ll];
    float Z = 0.f;
#pragma unroll
    for (int l = 0; l < Ll; l++) { ex[l] = expf(s_attn[l] - m); Z += ex[l]; }
    float invZ = 1.f / Z;
    float lv = 0.f;
#pragma unroll
    for (int l = 0; l < Ll; l++) lv += ex[l] * invZ * sb[l][d];

    float w1 = sigmoidf(user_wd[u * 8 + 2 * n]);
    float w2 = sigmoidf(user_wd[u * 8 + 2 * n + 1]);
    float coef = 1.f - w2 * w1;
    float h1 = sb[0][d];
#pragma unroll
    for (int l = 1; l < Ll; l++) h1 = w1 * h1 + coef * sb[l][d];
    float h2 = sb[Ll / 2][d];
#pragma unroll
    for (int l = Ll / 2 + 1; l < Ll; l++) h2 = w1 * h2 + coef * sb[l][d];
    float h3 = w1 * sb[Ll - 2][d] + coef * sb[Ll - 1][d];

    float a0 = alpha[0], a1 = alpha[1];
    float fn = h1 + a0 * (h1 - h2) + a1 * (h1 - h3);

    float gsum = block64_reduce(fn * gate_w[d] + lv * gate_w[Dd + d], sred, d);
    float g = sigmoidf(gsum + gate_b[0]);
    float fe = g * fn + (1.f - g) * lv;

    int off = nb * Dd + d;
    g_s1[off] = h1; g_s2[off] = h2; g_s3[off] = h3;
    g_lvec[off] = lv; g_feach[off] = fe;
}

// ---------------- kernel C: mixture over behaviors --------------------------
__global__ void __launch_bounds__(64)
k_mix(const int* __restrict__ userData, const float* __restrict__ user_emb,
      const float* __restrict__ w_mix, const float* __restrict__ alpha,
      const float* __restrict__ gate_w, const float* __restrict__ gate_b) {
    int b = blockIdx.x;
    int d = threadIdx.x;
    __shared__ float sred[Dd];

    float w[4][4];
#pragma unroll
    for (int i = 0; i < 4; i++) {
        float mx = -3.4e38f;
#pragma unroll
        for (int j = 0; j < 4; j++) mx = fmaxf(mx, w_mix[i * 4 + j]);
        float Z = 0.f;
#pragma unroll
        for (int j = 0; j < 4; j++) { w[i][j] = expf(w_mix[i * 4 + j] - mx); Z += w[i][j]; }
        float inv = 1.f / Z;
#pragma unroll
        for (int j = 0; j < 4; j++) w[i][j] *= inv;
    }

    float s1m = 0.f, s2m = 0.f, s3m = 0.f, lm = 0.f;
#pragma unroll
    for (int n = 0; n < 4; n++) {
        int off = (n * Bb + b) * Dd + d;
        s1m += w[0][n] * g_s1[off];
        s2m += w[1][n] * g_s2[off];
        s3m += w[2][n] * g_s3[off];
        lm  += w[3][n] * g_lvec[off];
    }
    float a0 = alpha[0], a1 = alpha[1];
    float fin_ = s1m + a0 * (s1m - s2m) + a1 * (s1m - s3m);

    float gsum = block64_reduce(fin_ * gate_w[d] + lm * gate_w[Dd + d], sred, d);
    float gm = sigmoidf(gsum + gate_b[0]);
    float fin = gm * fin_ + (1.f - gm) * lm;

    g_Afin[b * 128 + d] = fin;
    g_Afin[b * 128 + Dd + d] = user_emb[userData[b] * Dd + d];
}

// ---------------- kernel G: sparse old-items corrections --------------------
__global__ void __launch_bounds__(128)
k_sparse(const int* __restrict__ oldItems, const float* __restrict__ item_emb,
         float* __restrict__ out) {
    int b = blockIdx.x;
    int t = threadIdx.x;
    int n = t >> 5, lane = t & 31;
    __shared__ int sh_old[4][NOLDn];
    __shared__ float sh_fin[Dd];
    if (t < Dd) sh_fin[t] = g_Afin[b * 128 + t];
    if (t < 4 * NOLDn) {
        int n2 = t / NOLDn, j = t - n2 * NOLDn;
        sh_old[n2][j] = oldItems[(n2 * Bb + b) * NOLDn + j];
    }
    __syncthreads();

    int d0 = lane, d1 = lane + 32;
    float diff0 = g_feach[(n * Bb + b) * Dd + d0] - sh_fin[d0];
    float diff1 = g_feach[(n * Bb + b) * Dd + d1] - sh_fin[d1];
    const float* eall = item_emb + Dd;

    for (int j = 0; j < NOLDn; j++) {
        int e = sh_old[n][j];
        bool dup = false;
        for (int j2 = 0; j2 < j; j2++) if (sh_old[n][j2] == e) dup = true;
        if (dup) continue;
        float v = diff0 * eall[e * Dd + d0] + diff1 * eall[e * Dd + d1];
#pragma unroll
        for (int o = 16; o > 0; o >>= 1) v += __shfl_down_sync(0xffffffffu, v, o);
        if (lane == 0) atomicAdd(&out[(size_t)b * NB + e], v);
    }
}

// ---------------- kernel F: omiga copy ---------------------------------------
__global__ void k_omiga(const float* __restrict__ omiga, float* __restrict__ out) {
    int i = blockIdx.x * blockDim.x + threadIdx.x;
    if (i < NB) out[i] = omiga[i + 1];
}

// ---------------- launch ------------------------------------------------------
extern "C" void kernel_launch(void* const* d_in, const int* in_sizes, int n_in,
                              void* d_out, int out_size) {
    const int* click = (const int*)d_in[0];
    const int* favor = (const int*)d_in[1];
    const int* cart  = (const int*)d_in[2];
    const int* buy   = (const int*)d_in[3];
    const int* user  = (const int*)d_in[4];
    const int* olds  = (const int*)d_in[5];
    const float* item_emb = (const float*)d_in[6];
    const float* user_emb = (const float*)d_in[7];
    const float* user_wd  = (const float*)d_in[8];
    const float* omiga    = (const float*)d_in[9];
    const float* w_mix    = (const float*)d_in[10];
    const float* alpha    = (const float*)d_in[11];
    const float* gate_w   = (const float*)d_in[12];
    const float* gate_b   = (const float*)d_in[13];
    const float* Wk       = (const float*)d_in[14];
    const float* bk       = (const float*)d_in[15];
    const float* u_w      = (const float*)d_in[16];
    const float* u_b      = (const float*)d_in[17];
    float* out = (float*)d_out;

    const int MMA_SMEM = 2 * 17408 * 4;   // 139264 B
    static int attr_set = 0;
    cudaFuncSetAttribute(k_mma, cudaFuncAttributeMaxDynamicSharedMemorySize, MMA_SMEM);
    (void)attr_set;

    float *p_Afin, *p_uwT;
    cudaGetSymbolAddress((void**)&p_Afin, g_Afin);
    cudaGetSymbolAddress((void**)&p_uwT,  g_uwT);

    const float* e_all = item_emb + Dd;   // rows 1..12000

    k_baskets<<<4 * Bb * Ll / 4, 256>>>(click, favor, cart, buy, item_emb);
    k_seq<<<4 * Bb, 64>>>(user, user_emb, user_wd, Wk, bk, gate_w, gate_b, alpha);
    k_mix<<<Bb, 64>>>(user, user_emb, w_mix, alpha, gate_w, gate_b);
    k_uwT<<<dim3(NB / 32, 2), 1024>>>(u_w);

    // score = [final|e_user] @ [e_all^T ; u_w] + u_b  (two K=64 halves)
    {
        dim3 g((NB + 127) / 128, Bb / 128);   // 94 x 8
        k_mma<<<g, 256, MMA_SMEM>>>(p_Afin, p_Afin + 64, 128, (long)Bb,
                                    e_all, p_uwT, (long)NB,
                                    out, u_b, 0);
    }
    k_sparse<<<Bb, 128>>>(olds, item_emb, out);

    // sim = e_all @ e_all^T (triangular + mirror)
    {
        int nbT = (NB + 127) / 128;           // 94
        k_mma<<<nbT * (nbT + 1) / 2, 256, MMA_SMEM>>>(e_all, nullptr, 64, (long)NB,
                                                      e_all, nullptr, (long)NB,
                                                      out + (size_t)Bb * NB, nullptr, 1);
    }
    k_omiga<<<(NB + 255) / 256, 256>>>(omiga, out + (size_t)Bb * NB + (size_t)NB * NB);
}

// round 5
// speedup vs baseline: 2.1835x; 1.2604x over previous
#include <cuda_runtime.h>
#include <cuda_bf16.h>
#include <math.h>
#include <stdint.h>

#define NB   12000
#define Dd   64
#define Bb   1024
#define Ll   20
#define BKk  10
#define NOLDn 20
#define ROWU 40    // uint32 per smem tile row (32 data + 8 pad) = 160B

// ---------------- scratch (device globals; no allocation allowed) ----------
__device__ float g_baskets[4 * Bb * Ll * Dd];
__device__ float g_s1[4 * Bb * Dd];
__device__ float g_s2[4 * Bb * Dd];
__device__ float g_s3[4 * Bb * Dd];
__device__ float g_lvec[4 * Bb * Dd];
__device__ float g_feach[4 * Bb * Dd];
__device__ float g_Afin[Bb * 128];              // [final | e_user]
__device__ float g_uwT[NB * 64];                // u_w transposed: [e][k]

__device__ __forceinline__ float sigmoidf(float x) { return 1.f / (1.f + expf(-x)); }

// ===================== bf16x2 (split-2) mma.sync GEMM =======================
__device__ __forceinline__ void mma16(float* d, const uint32_t* a, const uint32_t* b) {
    asm volatile(
        "mma.sync.aligned.m16n8k16.row.col.f32.bf16.bf16.f32 "
        "{%0,%1,%2,%3}, {%4,%5,%6,%7}, {%8,%9}, {%0,%1,%2,%3};"
        : "+f"(d[0]), "+f"(d[1]), "+f"(d[2]), "+f"(d[3])
        : "r"(a[0]), "r"(a[1]), "r"(a[2]), "r"(a[3]), "r"(b[0]), "r"(b[1]));
}

__device__ __forceinline__ uint32_t packbf(__nv_bfloat16 lo, __nv_bfloat16 hi) {
    __nv_bfloat162 t = __halves2bfloat162(lo, hi);
    return *(uint32_t*)&t;
}

// pair-position permutation within each 16-k block: pp -> ((pp&3)<<1)|(pp>>2)
__device__ __forceinline__ int permpos(int pp) { return ((pp & 3) << 1) | (pp >> 2); }

// Load a 128x64 fp32 tile (rows clamped), split each value into two RN bf16
// (major D0, minor D1), store k-permuted so fragments are single LDS.64.
__device__ __forceinline__ void load_split_bf16(
    uint32_t* __restrict__ D0, uint32_t* __restrict__ D1,
    const float* __restrict__ src, long row0, long rows, int stride, int tid)
{
    int row = tid >> 1;            // 0..127
    int half = tid & 1;            // k base 0 / 32
    long gr = row0 + row; if (gr >= rows) gr = rows - 1;
    const float* base = src + gr * (long)stride + half * 32;
    uint32_t* d0 = D0 + row * ROWU + half * 16;
    uint32_t* d1 = D1 + row * ROWU + half * 16;
#pragma unroll
    for (int f = 0; f < 8; f++) {
        float4 v = *(const float4*)&base[f * 4];
        __nv_bfloat16 hx = __float2bfloat16_rn(v.x);
        __nv_bfloat16 hy = __float2bfloat16_rn(v.y);
        __nv_bfloat16 hz = __float2bfloat16_rn(v.z);
        __nv_bfloat16 hw = __float2bfloat16_rn(v.w);
        __nv_bfloat16 lx = __float2bfloat16_rn(v.x - __bfloat162float(hx));
        __nv_bfloat16 ly = __float2bfloat16_rn(v.y - __bfloat162float(hy));
        __nv_bfloat16 lz = __float2bfloat16_rn(v.z - __bfloat162float(hz));
        __nv_bfloat16 lw = __float2bfloat16_rn(v.w - __bfloat162float(hw));
        int kb = f >> 2;
        int pp0 = (f & 3) * 2;
        int o0 = kb * 8 + permpos(pp0);
        int o1 = kb * 8 + permpos(pp0 + 1);
        d0[o0] = packbf(hx, hy);
        d0[o1] = packbf(hz, hw);
        d1[o0] = packbf(lx, ly);
        d1[o1] = packbf(lz, lw);
    }
}

// Generic tile GEMM: C[i][j] = sum_h sum_k A_h[i][k] * B_h[j][k] (+ bias[j]).
// Tiles 128x128, K=64 per half (1 or 2 halves). triangular=1: linear
// upper-triangle tile id; result mirrored for off-diagonal tiles.
__global__ void __launch_bounds__(256, 2)
k_mma(const float* __restrict__ A1s, const float* __restrict__ A2s, int a_stride, long a_rows,
      const float* __restrict__ B1s, const float* __restrict__ B2s, long b_rows,
      float* __restrict__ C, const float* __restrict__ bias, int triangular)
{
    extern __shared__ uint32_t smu[];
    uint32_t* A0 = smu;            // 4 tiles x 5120 uint32 = 80KB
    uint32_t* A1 = smu + 5120;
    uint32_t* B0 = smu + 10240;
    uint32_t* B1 = smu + 15360;

    int tid = threadIdx.x;
    int bi, bj;
    if (triangular) {
        int lid = blockIdx.x;
        int r = (int)((sqrtf(8.f * (float)lid + 1.f) - 1.f) * 0.5f);
        while ((r + 1) * (r + 2) / 2 <= lid) r++;
        while (r * (r + 1) / 2 > lid) r--;
        bi = lid - r * (r + 1) / 2;
        bj = r;
    } else {
        bi = blockIdx.y; bj = blockIdx.x;
    }
    long i0 = (long)bi * 128, j0 = (long)bj * 128;

    int lane = tid & 31, wid = tid >> 5;
    int g = lane >> 2, tig = lane & 3;
    int wm = wid & 3, wn = wid >> 2;   // 4x2 warp grid -> 32x64 per warp

    float acc[2][8][4];
#pragma unroll
    for (int mt = 0; mt < 2; mt++)
#pragma unroll
        for (int nt = 0; nt < 8; nt++)
#pragma unroll
            for (int q = 0; q < 4; q++) acc[mt][nt][q] = 0.f;

    int halves = (A2s != nullptr) ? 2 : 1;
    for (int h = 0; h < halves; h++) {
        if (h) __syncthreads();
        load_split_bf16(A0, A1, h ? A2s : A1s, i0, a_rows, a_stride, tid);
        load_split_bf16(B0, B1, h ? B2s : B1s, j0, b_rows, 64, tid);
        __syncthreads();

#pragma unroll
        for (int s = 0; s < 4; s++) {
            uint32_t am[2][4], al[2][4];
#pragma unroll
            for (int mt = 0; mt < 2; mt++) {
                int r0 = wm * 32 + mt * 16 + g;
                uint2 u0 = *(const uint2*)(A0 + r0 * ROWU + s * 8 + tig * 2);
                uint2 u1 = *(const uint2*)(A0 + (r0 + 8) * ROWU + s * 8 + tig * 2);
                am[mt][0] = u0.x; am[mt][1] = u1.x; am[mt][2] = u0.y; am[mt][3] = u1.y;
                uint2 w0 = *(const uint2*)(A1 + r0 * ROWU + s * 8 + tig * 2);
                uint2 w1 = *(const uint2*)(A1 + (r0 + 8) * ROWU + s * 8 + tig * 2);
                al[mt][0] = w0.x; al[mt][1] = w1.x; al[mt][2] = w0.y; al[mt][3] = w1.y;
            }
#pragma unroll
            for (int nc = 0; nc < 2; nc++) {
                uint32_t bm[4][2], bl[4][2];
#pragma unroll
                for (int q = 0; q < 4; q++) {
                    int col = wn * 64 + (nc * 4 + q) * 8 + g;
                    uint2 u = *(const uint2*)(B0 + col * ROWU + s * 8 + tig * 2);
                    bm[q][0] = u.x; bm[q][1] = u.y;
                    uint2 w = *(const uint2*)(B1 + col * ROWU + s * 8 + tig * 2);
                    bl[q][0] = w.x; bl[q][1] = w.y;
                }
#pragma unroll
                for (int mt = 0; mt < 2; mt++)
#pragma unroll
                    for (int q = 0; q < 4; q++) {
                        float* a = acc[mt][nc * 4 + q];
                        mma16(a, am[mt], bm[q]);
                        mma16(a, am[mt], bl[q]);
                        mma16(a, al[mt], bm[q]);
                    }
            }
        }
    }

    // ---------------- epilogue: smem-staged coalesced stores ----------------
    float* st = (float*)smu;   // 128*133 = 17024 floats <= 20480
    __syncthreads();
#pragma unroll
    for (int mt = 0; mt < 2; mt++)
#pragma unroll
        for (int nt = 0; nt < 8; nt++) {
            int R  = wm * 32 + mt * 16 + g;
            int Cc = wn * 64 + nt * 8 + 2 * tig;
            st[R * 133 + Cc]           = acc[mt][nt][0];
            st[R * 133 + Cc + 1]       = acc[mt][nt][1];
            st[(R + 8) * 133 + Cc]     = acc[mt][nt][2];
            st[(R + 8) * 133 + Cc + 1] = acc[mt][nt][3];
        }
    __syncthreads();

    {
        int cc = tid & 127, rb = tid >> 7;
        long gj = j0 + cc;
        float bv = 0.f;
        if (bias && gj < b_rows) bv = bias[gj];
#pragma unroll 8
        for (int q = 0; q < 64; q++) {
            int r = rb + 2 * q;
            long gi = i0 + r;
            if (gi < a_rows && gj < b_rows)
                C[gi * (long)NB + gj] = st[r * 133 + cc] + bv;
        }
    }

    if (triangular && bi != bj) {
        __syncthreads();
#pragma unroll
        for (int mt = 0; mt < 2; mt++)
#pragma unroll
            for (int nt = 0; nt < 8; nt++) {
                int R  = wm * 32 + mt * 16 + g;
                int Cc = wn * 64 + nt * 8 + 2 * tig;
                st[Cc * 133 + R]           = acc[mt][nt][0];
                st[(Cc + 1) * 133 + R]     = acc[mt][nt][1];
                st[Cc * 133 + R + 8]       = acc[mt][nt][2];
                st[(Cc + 1) * 133 + R + 8] = acc[mt][nt][3];
            }
        __syncthreads();
        int ii = tid & 127, jb = tid >> 7;
        long gi = i0 + ii;
#pragma unroll 8
        for (int q = 0; q < 64; q++) {
            int jj = jb + 2 * q;
            long gj = j0 + jj;
            if (gi < a_rows && gj < b_rows)
                C[gj * (long)NB + gi] = st[jj * 133 + ii];
        }
    }
}

// ---------------- u_w transpose: g_uwT[e][k] = u_w[k][e] --------------------
__global__ void __launch_bounds__(1024)
k_uwT(const float* __restrict__ u_w) {
    __shared__ float t[32][33];
    int e0 = blockIdx.x * 32, k0 = blockIdx.y * 32;
    int tx = threadIdx.x & 31, ty = threadIdx.x >> 5;
    t[ty][tx] = u_w[(long)(k0 + ty) * NB + e0 + tx];
    __syncthreads();
    g_uwT[(long)(e0 + ty) * 64 + k0 + tx] = t[tx][ty];
}

// 64-thread block reduction (broadcast result to all threads)
__device__ __forceinline__ float block64_reduce(float v, float* sbuf, int d) {
    sbuf[d] = v;
    __syncthreads();
    if (d < 32) {
        float r = sbuf[d] + sbuf[d + 32];
#pragma unroll
        for (int o = 16; o > 0; o >>= 1) r += __shfl_down_sync(0xffffffffu, r, o);
        if (d == 0) sbuf[0] = r;
    }
    __syncthreads();
    float r = sbuf[0];
    __syncthreads();
    return r;
}

// ---------------- kernel A: baskets gather-sum ------------------------------
__global__ void k_baskets(const int* __restrict__ click, const int* __restrict__ favor,
                          const int* __restrict__ cart, const int* __restrict__ buy,
                          const float* __restrict__ item_emb) {
    int t = threadIdx.x;
    int d = t & 63;
    int row = blockIdx.x * 4 + (t >> 6);
    int n = row / (Bb * Ll);
    int rem = row - n * (Bb * Ll);
    const int* idx;
    if (n == 0) idx = click; else if (n == 1) idx = favor;
    else if (n == 2) idx = cart; else idx = buy;
    idx += rem * BKk;
    float s = 0.f;
#pragma unroll
    for (int k = 0; k < BKk; k++) s += item_emb[idx[k] * Dd + d];
    g_baskets[row * Dd + d] = s;
}

// ---------------- kernel B: per-(n,b) attention + EMA + gate ----------------
__global__ void __launch_bounds__(64)
k_seq(const int* __restrict__ userData, const float* __restrict__ user_emb,
      const float* __restrict__ user_wd, const float* __restrict__ Wk,
      const float* __restrict__ bk, const float* __restrict__ gate_w,
      const float* __restrict__ gate_b, const float* __restrict__ alpha) {
    int nb = blockIdx.x;
    int n = nb / Bb, b = nb - n * Bb;
    int d = threadIdx.x;

    __shared__ float sb[Ll][Dd];
    __shared__ float sred[Dd];
    __shared__ float s_attn[Ll];

    const float* bas = g_baskets + (size_t)nb * Ll * Dd;
#pragma unroll
    for (int l = 0; l < Ll; l++) sb[l][d] = bas[l * Dd + d];

    float wkreg[Dd];
#pragma unroll
    for (int e = 0; e < Dd; e++) wkreg[e] = Wk[n * Dd * Dd + e * Dd + d];

    int u = userData[b];
    float eu = user_emb[u * Dd + d];
    float bkd = bk[n * Dd + d];
    __syncthreads();

    for (int l = 0; l < Ll; l++) {
        float kd = bkd;
#pragma unroll
        for (int e = 0; e < Dd; e++) kd += sb[l][e] * wkreg[e];
        kd = fmaxf(kd, 0.f);
        float sc = block64_reduce(eu * kd, sred, d);
        float rs = block64_reduce(sb[l][d], sred, d);
        if (d == 0) s_attn[l] = (rs != 0.f) ? sc * 0.125f : -1000000000.0f;
        __syncthreads();
    }

    float m = -3.4e38f;
#pragma unroll
    for (int l = 0; l < Ll; l++) m = fmaxf(m, s_attn[l]);
    float ex[Ll];
    float Z = 0.f;
#pragma unroll
    for (int l = 0; l < Ll; l++) { ex[l] = expf(s_attn[l] - m); Z += ex[l]; }
    float invZ = 1.f / Z;
    float lv = 0.f;
#pragma unroll
    for (int l = 0; l < Ll; l++) lv += ex[l] * invZ * sb[l][d];

    float w1 = sigmoidf(user_wd[u * 8 + 2 * n]);
    float w2 = sigmoidf(user_wd[u * 8 + 2 * n + 1]);
    float coef = 1.f - w2 * w1;
    float h1 = sb[0][d];
#pragma unroll
    for (int l = 1; l < Ll; l++) h1 = w1 * h1 + coef * sb[l][d];
    float h2 = sb[Ll / 2][d];
#pragma unroll
    for (int l = Ll / 2 + 1; l < Ll; l++) h2 = w1 * h2 + coef * sb[l][d];
    float h3 = w1 * sb[Ll - 2][d] + coef * sb[Ll - 1][d];

    float a0 = alpha[0], a1 = alpha[1];
    float fn = h1 + a0 * (h1 - h2) + a1 * (h1 - h3);

    float gsum = block64_reduce(fn * gate_w[d] + lv * gate_w[Dd + d], sred, d);
    float g = sigmoidf(gsum + gate_b[0]);
    float fe = g * fn + (1.f - g) * lv;

    int off = nb * Dd + d;
    g_s1[off] = h1; g_s2[off] = h2; g_s3[off] = h3;
    g_lvec[off] = lv; g_feach[off] = fe;
}

// ---------------- kernel C: mixture over behaviors --------------------------
__global__ void __launch_bounds__(64)
k_mix(const int* __restrict__ userData, const float* __restrict__ user_emb,
      const float* __restrict__ w_mix, const float* __restrict__ alpha,
      const float* __restrict__ gate_w, const float* __restrict__ gate_b) {
    int b = blockIdx.x;
    int d = threadIdx.x;
    __shared__ float sred[Dd];

    float w[4][4];
#pragma unroll
    for (int i = 0; i < 4; i++) {
        float mx = -3.4e38f;
#pragma unroll
        for (int j = 0; j < 4; j++) mx = fmaxf(mx, w_mix[i * 4 + j]);
        float Z = 0.f;
#pragma unroll
        for (int j = 0; j < 4; j++) { w[i][j] = expf(w_mix[i * 4 + j] - mx); Z += w[i][j]; }
        float inv = 1.f / Z;
#pragma unroll
        for (int j = 0; j < 4; j++) w[i][j] *= inv;
    }

    float s1m = 0.f, s2m = 0.f, s3m = 0.f, lm = 0.f;
#pragma unroll
    for (int n = 0; n < 4; n++) {
        int off = (n * Bb + b) * Dd + d;
        s1m += w[0][n] * g_s1[off];
        s2m += w[1][n] * g_s2[off];
        s3m += w[2][n] * g_s3[off];
        lm  += w[3][n] * g_lvec[off];
    }
    float a0 = alpha[0], a1 = alpha[1];
    float fin_ = s1m + a0 * (s1m - s2m) + a1 * (s1m - s3m);

    float gsum = block64_reduce(fin_ * gate_w[d] + lm * gate_w[Dd + d], sred, d);
    float gm = sigmoidf(gsum + gate_b[0]);
    float fin = gm * fin_ + (1.f - gm) * lm;

    g_Afin[b * 128 + d] = fin;
    g_Afin[b * 128 + Dd + d] = user_emb[userData[b] * Dd + d];
}

// ---------------- kernel G: sparse old-items corrections --------------------
__global__ void __launch_bounds__(128)
k_sparse(const int* __restrict__ oldItems, const float* __restrict__ item_emb,
         float* __restrict__ out) {
    int b = blockIdx.x;
    int t = threadIdx.x;
    int n = t >> 5, lane = t & 31;
    __shared__ int sh_old[4][NOLDn];
    __shared__ float sh_fin[Dd];
    if (t < Dd) sh_fin[t] = g_Afin[b * 128 + t];
    if (t < 4 * NOLDn) {
        int n2 = t / NOLDn, j = t - n2 * NOLDn;
        sh_old[n2][j] = oldItems[(n2 * Bb + b) * NOLDn + j];
    }
    __syncthreads();

    int d0 = lane, d1 = lane + 32;
    float diff0 = g_feach[(n * Bb + b) * Dd + d0] - sh_fin[d0];
    float diff1 = g_feach[(n * Bb + b) * Dd + d1] - sh_fin[d1];
    const float* eall = item_emb + Dd;

    for (int j = 0; j < NOLDn; j++) {
        int e = sh_old[n][j];
        bool dup = false;
        for (int j2 = 0; j2 < j; j2++) if (sh_old[n][j2] == e) dup = true;
        if (dup) continue;
        float v = diff0 * eall[e * Dd + d0] + diff1 * eall[e * Dd + d1];
#pragma unroll
        for (int o = 16; o > 0; o >>= 1) v += __shfl_down_sync(0xffffffffu, v, o);
        if (lane == 0) atomicAdd(&out[(size_t)b * NB + e], v);
    }
}

// ---------------- kernel F: omiga copy ---------------------------------------
__global__ void k_omiga(const float* __restrict__ omiga, float* __restrict__ out) {
    int i = blockIdx.x * blockDim.x + threadIdx.x;
    if (i < NB) out[i] = omiga[i + 1];
}

// ---------------- launch ------------------------------------------------------
extern "C" void kernel_launch(void* const* d_in, const int* in_sizes, int n_in,
                              void* d_out, int out_size) {
    const int* click = (const int*)d_in[0];
    const int* favor = (const int*)d_in[1];
    const int* cart  = (const int*)d_in[2];
    const int* buy   = (const int*)d_in[3];
    const int* user  = (const int*)d_in[4];
    const int* olds  = (const int*)d_in[5];
    const float* item_emb = (const float*)d_in[6];
    const float* user_emb = (const float*)d_in[7];
    const float* user_wd  = (const float*)d_in[8];
    const float* omiga    = (const float*)d_in[9];
    const float* w_mix    = (const float*)d_in[10];
    const float* alpha    = (const float*)d_in[11];
    const float* gate_w   = (const float*)d_in[12];
    const float* gate_b   = (const float*)d_in[13];
    const float* Wk       = (const float*)d_in[14];
    const float* bk       = (const float*)d_in[15];
    const float* u_w      = (const float*)d_in[16];
    const float* u_b      = (const float*)d_in[17];
    float* out = (float*)d_out;

    const int MMA_SMEM = 4 * 5120 * 4;   // 81920 B
    cudaFuncSetAttribute(k_mma, cudaFuncAttributeMaxDynamicSharedMemorySize, MMA_SMEM);

    float *p_Afin, *p_uwT;
    cudaGetSymbolAddress((void**)&p_Afin, g_Afin);
    cudaGetSymbolAddress((void**)&p_uwT,  g_uwT);

    const float* e_all = item_emb + Dd;   // rows 1..12000

    k_baskets<<<4 * Bb * Ll / 4, 256>>>(click, favor, cart, buy, item_emb);
    k_seq<<<4 * Bb, 64>>>(user, user_emb, user_wd, Wk, bk, gate_w, gate_b, alpha);
    k_mix<<<Bb, 64>>>(user, user_emb, w_mix, alpha, gate_w, gate_b);

    // sim = e_all @ e_all^T (triangular + mirror)  [position 4 -> gets profiled]
    {
        int nbT = (NB + 127) / 128;           // 94
        k_mma<<<nbT * (nbT + 1) / 2, 256, MMA_SMEM>>>(e_all, nullptr, 64, (long)NB,
                                                      e_all, nullptr, (long)NB,
                                                      out + (size_t)Bb * NB, nullptr, 1);
    }

    k_uwT<<<dim3(NB / 32, 2), 1024>>>(u_w);

    // score = [final|e_user] @ [e_all^T ; u_w] + u_b  (two K=64 halves)
    {
        dim3 g((NB + 127) / 128, Bb / 128);   // 94 x 8
        k_mma<<<g, 256, MMA_SMEM>>>(p_Afin, p_Afin + 64, 128, (long)Bb,
                                    e_all, p_uwT, (long)NB,
                                    out, u_b, 0);
    }
    k_sparse<<<Bb, 128>>>(olds, item_emb, out);
    k_omiga<<<(NB + 255) / 256, 256>>>(omiga, out + (size_t)Bb * NB + (size_t)NB * NB);
}